// round 15
// baseline (speedup 1.0000x reference)
#include <cuda_runtime.h>
#include <cuda_fp16.h>
#include <cstdint>
#include <math.h>

#define NB 64
#define NT 256
#define ND 512

// fp16 scratch: sqrt(w)-scaled + RN-rounded, NATIVE layout [b][t][d]
__device__ __half g_rh[(size_t)NB * NT * ND];
__device__ __half g_ih[(size_t)NB * NT * ND];

// ---------- helpers ----------
__device__ __forceinline__ uint32_t s2u(const void* p) {
    uint32_t a;
    asm("{ .reg .u64 t; cvta.to.shared.u64 t, %1; cvt.u32.u64 %0, t; }" : "=r"(a) : "l"(p));
    return a;
}
__device__ __forceinline__ void cpa16(uint32_t dst, const void* src) {
    asm volatile("cp.async.cg.shared.global [%0], [%1], 16;" :: "r"(dst), "l"(src));
}
__device__ __forceinline__ void ldsm4t(uint32_t r[4], uint32_t addr) {
    asm volatile("ldmatrix.sync.aligned.m8n8.x4.trans.shared.b16 {%0,%1,%2,%3}, [%4];"
                 : "=r"(r[0]), "=r"(r[1]), "=r"(r[2]), "=r"(r[3]) : "r"(addr));
}
__device__ __forceinline__ void mma16816(float c[4], const uint32_t a[4],
                                         uint32_t b0, uint32_t b1) {
    asm volatile(
        "mma.sync.aligned.m16n8k16.row.col.f32.f16.f16.f32 "
        "{%0,%1,%2,%3}, {%4,%5,%6,%7}, {%8,%9}, {%0,%1,%2,%3};"
        : "+f"(c[0]), "+f"(c[1]), "+f"(c[2]), "+f"(c[3])
        : "r"(a[0]), "r"(a[1]), "r"(a[2]), "r"(a[3]), "r"(b0), "r"(b1));
}

// ---------- Pass 1: element-wise sqrt(w) scale + fp16 round ----------
__global__ void __launch_bounds__(128) prep_kernel(
    const float* __restrict__ real, const float* __restrict__ imag,
    const float* __restrict__ weight) {
    int row = blockIdx.x;  // b*NT + t
    float s = sqrtf(weight[row]);
    size_t base = (size_t)row * ND;
    int j = threadIdx.x;
    float4 r = reinterpret_cast<const float4*>(real + base)[j];
    float4 im = reinterpret_cast<const float4*>(imag + base)[j];
    __half2 ra = __floats2half2_rn(r.x * s, r.y * s);
    __half2 rb = __floats2half2_rn(r.z * s, r.w * s);
    __half2 ia = __floats2half2_rn(im.x * s, im.y * s);
    __half2 ib = __floats2half2_rn(im.z * s, im.w * s);
    uint2 rv = make_uint2(*reinterpret_cast<uint32_t*>(&ra), *reinterpret_cast<uint32_t*>(&rb));
    uint2 iv = make_uint2(*reinterpret_cast<uint32_t*>(&ia), *reinterpret_cast<uint32_t*>(&ib));
    *reinterpret_cast<uint2*>(g_rh + base + j * 4) = rv;
    *reinterpret_cast<uint2*>(g_ih + base + j * 4) = iv;
}

// ---------- Pass 2: fp16 mma.sync, 128x64 tiles, K-chunk 64, 2 CTAs/SM ----------
#define AROW_B 272                   // 128 cols * 2B + 16 pad
#define BROW_B 144                   // 64 cols * 2B + 16 pad
#define AOFF0 0
#define AOFF1 (64 * AROW_B)          // 17408
#define BOFF0 (2 * 64 * AROW_B)      // 34816
#define BOFF1 (BOFF0 + 64 * BROW_B)  // 44032
#define STAGE_B (BOFF1 + 64 * BROW_B)  // 53248
#define NSTAGE 2
#define SMEM_REQ (NSTAGE * STAGE_B)    // 106496 (>= 2 * 128*65*4 = 66560)

__global__ void __launch_bounds__(256, 2) gemm_kernel(float* __restrict__ out) {
    extern __shared__ char smem[];
    uint32_t sb = s2u(smem);
    int tid = threadIdx.x, lane = tid & 31, wid = tid >> 5;
    int wm = wid & 3, wn = wid >> 2;  // 4 x 2 warp grid, 32x32 per warp
    int b = blockIdx.z;
    int bx = blockIdx.x;
    const int ODI[6] = {0, 0, 0, 1, 1, 2};
    const int OEI[6] = {1, 2, 3, 2, 3, 3};
    bool mirror = (bx < 12);
    int di, ei, h;
    if (mirror) { di = ODI[bx >> 1]; ei = OEI[bx >> 1]; h = bx & 1; }
    else        { int q = bx - 12; di = q >> 1; ei = q >> 1; h = q & 1; }

    const __half* a_r = g_rh + (size_t)b * NT * ND + di * 128;
    const __half* a_i = g_ih + (size_t)b * NT * ND + di * 128;
    const __half* b_r = g_rh + (size_t)b * NT * ND + ei * 128 + h * 64;
    const __half* b_i = g_ih + (size_t)b * NT * ND + ei * 128 + h * 64;

    int jr = tid & 15, rr = tid >> 4;   // A: 16B chunk (0..15) / row base (0..15)
    int jb = tid & 7,  rb_ = tid >> 3;  // B: 16B chunk (0..7)  / row (0..31)

    // one K-chunk = 64 t-rows; 12 cp.async per thread
    auto issue = [&](int c, int s) {
        uint32_t st = sb + (uint32_t)s * STAGE_B;
#pragma unroll
        for (int rep = 0; rep < 4; rep++) {
            int row = rep * 16 + rr;
            cpa16(st + AOFF0 + (uint32_t)(row * AROW_B + jr * 16),
                  a_r + (size_t)(c * 64 + row) * ND + jr * 8);
            cpa16(st + AOFF1 + (uint32_t)(row * AROW_B + jr * 16),
                  a_i + (size_t)(c * 64 + row) * ND + jr * 8);
        }
#pragma unroll
        for (int rep = 0; rep < 2; rep++) {
            int row = rep * 32 + rb_;
            cpa16(st + BOFF0 + (uint32_t)(row * BROW_B + jb * 16),
                  b_r + (size_t)(c * 64 + row) * ND + jb * 8);
            cpa16(st + BOFF1 + (uint32_t)(row * BROW_B + jb * 16),
                  b_i + (size_t)(c * 64 + row) * ND + jb * 8);
        }
        asm volatile("cp.async.commit_group;" ::: "memory");
    };

    float accS[2][4][4], accD[2][4][4];
#pragma unroll
    for (int mt = 0; mt < 2; mt++)
#pragma unroll
        for (int nt = 0; nt < 4; nt++)
#pragma unroll
            for (int q = 0; q < 4; q++) { accS[mt][nt][q] = 0.f; accD[mt][nt][q] = 0.f; }

    int kbase = (lane >> 4) * 8 + (lane & 7);
    int csel = ((lane >> 3) & 1) * 8;

    issue(0, 0);
    for (int c = 0; c < 4; c++) {
        int s = c & 1;
        asm volatile("cp.async.wait_group 0;" ::: "memory");
        __syncthreads();  // chunk c data visible to all; prior stage reads done
        if (c < 3) issue(c + 1, s ^ 1);  // prefetch next chunk (full epoch ahead)
        uint32_t stb = sb + (uint32_t)s * STAGE_B;
#pragma unroll
        for (int kk = 0; kk < 4; kk++) {
            uint32_t krowA = (uint32_t)((kk * 16 + kbase) * AROW_B);
            uint32_t krowB = (uint32_t)((kk * 16 + kbase) * BROW_B);
            uint32_t rA[2][4], iA[2][4];
#pragma unroll
            for (int mt = 0; mt < 2; mt++) {
                uint32_t co = (uint32_t)((wm * 32 + mt * 16 + csel) * 2);
                ldsm4t(rA[mt], stb + AOFF0 + krowA + co);
                ldsm4t(iA[mt], stb + AOFF1 + krowA + co);
            }
            uint32_t rB[2][4], iB[2][4];
#pragma unroll
            for (int p = 0; p < 2; p++) {
                uint32_t co = (uint32_t)((wn * 32 + p * 16 + csel) * 2);
                ldsm4t(rB[p], stb + BOFF0 + krowB + co);
                ldsm4t(iB[p], stb + BOFF1 + krowB + co);
            }
            // S += r.r + i.i
#pragma unroll
            for (int mt = 0; mt < 2; mt++)
#pragma unroll
                for (int p = 0; p < 2; p++) {
                    mma16816(accS[mt][2 * p + 0], rA[mt], rB[p][0], rB[p][2]);
                    mma16816(accS[mt][2 * p + 1], rA[mt], rB[p][1], rB[p][3]);
                    mma16816(accS[mt][2 * p + 0], iA[mt], iB[p][0], iB[p][2]);
                    mma16816(accS[mt][2 * p + 1], iA[mt], iB[p][1], iB[p][3]);
                }
            // negate rA (fp16x2 sign flip), then D += i.r + (-r).i
#pragma unroll
            for (int mt = 0; mt < 2; mt++)
#pragma unroll
                for (int q = 0; q < 4; q++) rA[mt][q] ^= 0x80008000u;
#pragma unroll
            for (int mt = 0; mt < 2; mt++)
#pragma unroll
                for (int p = 0; p < 2; p++) {
                    mma16816(accD[mt][2 * p + 0], iA[mt], rB[p][0], rB[p][2]);
                    mma16816(accD[mt][2 * p + 1], iA[mt], rB[p][1], rB[p][3]);
                    mma16816(accD[mt][2 * p + 0], rA[mt], iB[p][0], iB[p][2]);
                    mma16816(accD[mt][2 * p + 1], rA[mt], iB[p][1], iB[p][3]);
                }
        }
    }

    // ---- Epilogue: direct tile (d rows, e cols) ----
    size_t ob = (size_t)NB * ND * ND;
    int ecol0 = ei * 128 + h * 64;
#pragma unroll
    for (int mt = 0; mt < 2; mt++) {
        int gd = di * 128 + wm * 32 + mt * 16 + (lane >> 2);
#pragma unroll
        for (int nt = 0; nt < 4; nt++) {
            int ge = ecol0 + wn * 32 + nt * 8 + (lane & 3) * 2;
            float* pr = out + ((size_t)b * ND + gd) * ND + ge;
            *reinterpret_cast<float2*>(pr) = make_float2(accS[mt][nt][0], accS[mt][nt][1]);
            *reinterpret_cast<float2*>(pr + 8 * ND) = make_float2(accS[mt][nt][2], accS[mt][nt][3]);
            float* pi = pr + ob;
            *reinterpret_cast<float2*>(pi) = make_float2(accD[mt][nt][0], accD[mt][nt][1]);
            *reinterpret_cast<float2*>(pi + 8 * ND) = make_float2(accD[mt][nt][2], accD[mt][nt][3]);
        }
    }

    // ---- Mirrored tile via merged SMEM transpose (off-diagonal only) ----
    if (mirror) {
        float* ts0 = reinterpret_cast<float*>(smem);  // [128][65] S
        float* ts1 = ts0 + 128 * 65;                  // [128][65] D
        __syncthreads();
#pragma unroll
        for (int mt = 0; mt < 2; mt++) {
            int gdl = wm * 32 + mt * 16 + (lane >> 2);
#pragma unroll
            for (int nt = 0; nt < 4; nt++) {
                int gel = wn * 32 + nt * 8 + (lane & 3) * 2;
                ts0[gdl * 65 + gel]           = accS[mt][nt][0];
                ts0[gdl * 65 + gel + 1]       = accS[mt][nt][1];
                ts0[(gdl + 8) * 65 + gel]     = accS[mt][nt][2];
                ts0[(gdl + 8) * 65 + gel + 1] = accS[mt][nt][3];
                ts1[gdl * 65 + gel]           = accD[mt][nt][0];
                ts1[gdl * 65 + gel + 1]       = accD[mt][nt][1];
                ts1[(gdl + 8) * 65 + gel]     = accD[mt][nt][2];
                ts1[(gdl + 8) * 65 + gel + 1] = accD[mt][nt][3];
            }
        }
        __syncthreads();
#pragma unroll
        for (int it = 0; it < 8; it++) {
            int e = tid >> 2;                 // 0..63
            int d = (it * 4 + (tid & 3)) * 4; // 0..124
            float4 v, u;
            v.x = ts0[(d + 0) * 65 + e];
            v.y = ts0[(d + 1) * 65 + e];
            v.z = ts0[(d + 2) * 65 + e];
            v.w = ts0[(d + 3) * 65 + e];
            u.x = -ts1[(d + 0) * 65 + e];
            u.y = -ts1[(d + 1) * 65 + e];
            u.z = -ts1[(d + 2) * 65 + e];
            u.w = -ts1[(d + 3) * 65 + e];
            size_t rowo = ((size_t)b * ND + ecol0 + e) * ND + di * 128 + d;
            *reinterpret_cast<float4*>(out + rowo) = v;
            *reinterpret_cast<float4*>(out + ob + rowo) = u;
        }
    }
}

extern "C" void kernel_launch(void* const* d_in, const int* in_sizes, int n_in,
                              void* d_out, int out_size) {
    const float* real = (const float*)d_in[0];
    const float* imag = (const float*)d_in[1];
    const float* weight = (const float*)d_in[2];
    float* out = (float*)d_out;

    cudaFuncSetAttribute(gemm_kernel, cudaFuncAttributeMaxDynamicSharedMemorySize, SMEM_REQ);

    prep_kernel<<<NB * NT, 128>>>(real, imag, weight);

    dim3 g2(20, 1, NB);  // 12 off-diag halves + 8 diag halves, x 64 batches
    gemm_kernel<<<g2, 256, SMEM_REQ>>>(out);
}